// round 1
// baseline (speedup 1.0000x reference)
#include <cuda_runtime.h>
#include <math.h>

#define HH   128
#define NHD  2
#define HDd  64
#define BB   8
#define LLs  200
#define TVC  32
#define NROWS (BB*LLs)   // 1600

// scratch (device globals: no allocation allowed)
__device__ float g_q  [NROWS*HH];
__device__ float g_kk [NROWS*HH];
__device__ float g_vv [NROWS*HH];
__device__ float g_ctx[NROWS*HH];

// ---------------------------------------------------------------------------
// Kernel 1: fused QKV projection (+bias, +pos tables folded into K and V)
// grid (100, 3), block 128.  m=0:Q  m=1:K(+kpos)  m=2:V(+vpos)
// ---------------------------------------------------------------------------
__global__ void proj_kernel(const float* __restrict__ X,
                            const float* __restrict__ Wq, const float* __restrict__ bq,
                            const float* __restrict__ Wk, const float* __restrict__ bk,
                            const float* __restrict__ Wv, const float* __restrict__ bv,
                            const float* __restrict__ kpos, const float* __restrict__ vpos)
{
    const int m  = blockIdx.y;
    const int r0 = blockIdx.x * 16;
    const int j  = threadIdx.x;   // output column 0..127

    __shared__ float xs[16*128];
    for (int idx = j; idx < 16*128; idx += 128)
        xs[idx] = X[r0*128 + idx];
    __syncthreads();

    const float* W    = (m==0) ? Wq : (m==1 ? Wk : Wv);
    const float* bias = (m==0) ? bq : (m==1 ? bk : bv);

    float acc[16];
    #pragma unroll
    for (int r = 0; r < 16; r++) acc[r] = 0.f;

    const float4* xs4 = (const float4*)xs;
    #pragma unroll 4
    for (int i = 0; i < 128; i += 4) {
        float w0 = W[(i+0)*128 + j];
        float w1 = W[(i+1)*128 + j];
        float w2 = W[(i+2)*128 + j];
        float w3 = W[(i+3)*128 + j];
        #pragma unroll
        for (int r = 0; r < 16; r++) {
            float4 xv = xs4[r*32 + (i>>2)];
            acc[r] += xv.x*w0 + xv.y*w1 + xv.z*w2 + xv.w*w3;
        }
    }

    float bj = bias[j];
    float* out = (m==0) ? g_q : (m==1 ? g_kk : g_vv);
    #pragma unroll
    for (int r = 0; r < 16; r++) {
        int row = r0 + r;
        float v = acc[r] + bj;
        if (m == 1)      v += kpos[(row % LLs)*128 + j];
        else if (m == 2) v += vpos[(row % LLs)*128 + j];
        out[row*128 + j] = v;
    }
}

// ---------------------------------------------------------------------------
// Kernel 2: attention. grid (8 q-tiles, NH, B), block 256, dynamic smem.
// smem float offsets:
//   kk   0      (200*68)      vv   13600 (200*68)
//   kt   27200  (32*68)       vt   29376 (32*68)
//   tv   31552  (200 int)     qrow 31752 (64)
//   ts   31816  (32)          sd   31848 (200)
//   pd   32048  (200)         ixa  32248 (200 int)
//   cpar 32448  (256)         cbin 32704 (32)
//   pA   32736  (512 = 8x32 float2)   pB 33248 (512)
//   red  33760  (16)
// total 33776 floats -> 135104 B
// ---------------------------------------------------------------------------
#define SMEM_FLOATS 33776

__device__ __forceinline__ float blockReduce(float v, float* red, int tid, bool ismax)
{
    #pragma unroll
    for (int o = 16; o > 0; o >>= 1) {
        float t = __shfl_xor_sync(0xffffffffu, v, o);
        v = ismax ? fmaxf(v, t) : (v + t);
    }
    if ((tid & 31) == 0) red[tid >> 5] = v;
    __syncthreads();
    if (tid == 0) {
        float a = red[0];
        #pragma unroll
        for (int i = 1; i < 8; i++) a = ismax ? fmaxf(a, red[i]) : (a + red[i]);
        red[8] = a;
    }
    __syncthreads();
    return red[8];
}

__global__ void attn_kernel(const float* __restrict__ maskg,
                            const void*  __restrict__ tsq,
                            const float* __restrict__ KTg,
                            const float* __restrict__ VTg)
{
    extern __shared__ float sm[];
    const int qt  = blockIdx.x;       // 0..7 (25 q rows each)
    const int h   = blockIdx.y;
    const int b   = blockIdx.z;
    const int tid = threadIdx.x;

    float* kk   = sm;
    float* vv   = sm + 13600;
    float* kt   = sm + 27200;
    float* vt   = sm + 29376;
    int*   tv   = (int*)(sm + 31552);
    float* qrow = sm + 31752;
    float* ts   = sm + 31816;
    float* sd   = sm + 31848;
    float* pd   = sm + 32048;
    int*   ixa  = (int*)(sm + 32248);
    float* cpar = sm + 32448;
    float* cbin = sm + 32704;
    float2* pA  = (float2*)(sm + 32736);
    float2* pB  = (float2*)(sm + 33248);
    float* red  = sm + 33760;

    // stage K,V head slices (stride 68 to avoid bank conflicts)
    const float* kkg = g_kk + (size_t)(b*LLs)*HH + h*HDd;
    const float* vvg = g_vv + (size_t)(b*LLs)*HH + h*HDd;
    for (int idx = tid; idx < LLs*HDd; idx += 256) {
        int k = idx >> 6, d = idx & 63;
        kk[k*68 + d] = kkg[k*HH + d];
        vv[k*68 + d] = vvg[k*HH + d];
    }
    for (int idx = tid; idx < TVC*HDd; idx += 256) {
        int w = idx >> 6, d = idx & 63;
        kt[w*68 + d] = KTg[w*HH + h*HDd + d];
        vt[w*68 + d] = VTg[w*HH + h*HDd + d];
    }
    // time values: detect int64 vs int32 storage.
    // int32 case: element 199 = max of sorted row 0 (>0).
    // int64 case: word 199 = high word of a value <2^31 -> 0.
    {
        const int* t32 = (const int*)tsq;
        bool is64 = (t32[2*100 - 1] == 0);
        for (int k = tid; k < LLs; k += 256) {
            long long t = is64 ? ((const long long*)tsq)[b*LLs + k]
                               : (long long)t32[b*LLs + k];
            tv[k] = (int)t;
        }
    }
    __syncthreads();

    const float* qg = g_q + (size_t)(b*LLs)*HH + h*HDd;

    for (int ql = 0; ql < 25; ql++) {
        const int qi = qt*25 + ql;

        if (tid < 64) qrow[tid] = qg[qi*HH + tid];
        __syncthreads();

        // ts[w] = q . KT[w]
        if (tid < 32) {
            const float4* q4  = (const float4*)qrow;
            const float4* ktr = (const float4*)(kt + tid*68);
            float a = 0.f;
            #pragma unroll
            for (int i = 0; i < 16; i++) {
                float4 x = q4[i], y = ktr[i];
                a += x.x*y.x + x.y*y.y + x.z*y.z + x.w*y.w;
            }
            ts[tid] = a;
        }
        __syncthreads();

        // scores over k
        float sv = -1e30f;
        if (tid < LLs) {
            const float4* q4 = (const float4*)qrow;
            const float4* kr = (const float4*)(kk + tid*68);
            float a = 0.f;
            #pragma unroll
            for (int i = 0; i < 16; i++) {
                float4 x = q4[i], y = kr[i];
                a += x.x*y.x + x.y*y.y + x.z*y.z + x.w*y.w;
            }
            int dt = tv[qi] - tv[tid]; if (dt < 0) dt = -dt;
            int ix = (int)log1pf((float)dt);
            float s = (a + ts[ix]) * 0.125f
                      + maskg[((size_t)(b*LLs) + qi)*LLs + tid];
            sd[tid]  = s;
            ixa[tid] = ix;
            sv = s;
        }

        float mx = blockReduce(sv, red, tid, true);
        float ev = (tid < LLs) ? expf(sv - mx) : 0.f;
        float sum = blockReduce(ev, red, tid, false);
        float rs = 1.f / sum;
        if (tid < LLs) pd[tid] = ev * rs;
        __syncthreads();

        // bin scores by time index: cbin[w] = sum_{k: idx==w} sd[k]
        {
            int w = tid & 31, kc = tid >> 5;
            float a = 0.f;
            int k0 = kc * 25;
            #pragma unroll 5
            for (int k = k0; k < k0 + 25; k++)
                a += (ixa[k] == w) ? sd[k] : 0.f;
            cpar[kc*32 + w] = a;
        }
        __syncthreads();
        if (tid < 32) {
            float a = 0.f;
            #pragma unroll
            for (int kc = 0; kc < 8; kc++) a += cpar[kc*32 + tid];
            cbin[tid] = a;
        }
        __syncthreads();

        // context: ctx = p @ vv + cbin @ vt   (float2 over d)
        {
            int d2 = tid & 31, kc = tid >> 5;
            float2 a; a.x = 0.f; a.y = 0.f;
            int k0 = kc * 25;
            #pragma unroll 5
            for (int k = k0; k < k0 + 25; k++) {
                float p = pd[k];
                float2 v = *(const float2*)(vv + k*68 + d2*2);
                a.x += p * v.x; a.y += p * v.y;
            }
            pA[kc*32 + d2] = a;

            float2 bacc; bacc.x = 0.f; bacc.y = 0.f;
            int w0 = kc * 4;
            #pragma unroll
            for (int w = w0; w < w0 + 4; w++) {
                float cw = cbin[w];
                float2 v = *(const float2*)(vt + w*68 + d2*2);
                bacc.x += cw * v.x; bacc.y += cw * v.y;
            }
            pB[kc*32 + d2] = bacc;
        }
        __syncthreads();
        if (tid < 32) {
            float2 a; a.x = 0.f; a.y = 0.f;
            #pragma unroll
            for (int kc = 0; kc < 8; kc++) {
                float2 x = pA[kc*32 + tid]; a.x += x.x; a.y += x.y;
                float2 y = pB[kc*32 + tid]; a.x += y.x; a.y += y.y;
            }
            *(float2*)(g_ctx + ((size_t)(b*LLs) + qi)*HH + h*HDd + 2*tid) = a;
        }
        __syncthreads();
    }
}

// ---------------------------------------------------------------------------
// Kernel 3: output projection + bias + residual + LayerNorm
// grid 100, block 128 (thread = output column)
// ---------------------------------------------------------------------------
__global__ void out_kernel(const float* __restrict__ X,
                           const float* __restrict__ Wd, const float* __restrict__ bd,
                           const float* __restrict__ lng, const float* __restrict__ lnb,
                           float* __restrict__ out)
{
    const int r0 = blockIdx.x * 16;
    const int j  = threadIdx.x;
    const int lane = j & 31, wrp = j >> 5;

    __shared__ float cs[16*128];
    __shared__ float wsum[16*4];

    for (int idx = j; idx < 16*128; idx += 128)
        cs[idx] = g_ctx[r0*128 + idx];
    __syncthreads();

    float acc[16];
    #pragma unroll
    for (int r = 0; r < 16; r++) acc[r] = 0.f;

    const float4* cs4 = (const float4*)cs;
    #pragma unroll 4
    for (int i = 0; i < 128; i += 4) {
        float w0 = Wd[(i+0)*128 + j];
        float w1 = Wd[(i+1)*128 + j];
        float w2 = Wd[(i+2)*128 + j];
        float w3 = Wd[(i+3)*128 + j];
        #pragma unroll
        for (int r = 0; r < 16; r++) {
            float4 xv = cs4[r*32 + (i>>2)];
            acc[r] += xv.x*w0 + xv.y*w1 + xv.z*w2 + xv.w*w3;
        }
    }

    float bj = bd[j];
    float hid[16];
    #pragma unroll
    for (int r = 0; r < 16; r++)
        hid[r] = acc[r] + bj + X[(r0 + r)*128 + j];

    // mean
    #pragma unroll
    for (int r = 0; r < 16; r++) {
        float v = hid[r];
        #pragma unroll
        for (int o = 16; o > 0; o >>= 1) v += __shfl_xor_sync(0xffffffffu, v, o);
        if (lane == 0) wsum[r*4 + wrp] = v;
    }
    __syncthreads();
    float mu[16];
    #pragma unroll
    for (int r = 0; r < 16; r++)
        mu[r] = (wsum[r*4] + wsum[r*4+1] + wsum[r*4+2] + wsum[r*4+3]) * (1.f/128.f);
    __syncthreads();
    // variance
    #pragma unroll
    for (int r = 0; r < 16; r++) {
        float d = hid[r] - mu[r];
        float v = d * d;
        #pragma unroll
        for (int o = 16; o > 0; o >>= 1) v += __shfl_xor_sync(0xffffffffu, v, o);
        if (lane == 0) wsum[r*4 + wrp] = v;
    }
    __syncthreads();

    float gj = lng[j], bbj = lnb[j];
    #pragma unroll
    for (int r = 0; r < 16; r++) {
        float var = (wsum[r*4] + wsum[r*4+1] + wsum[r*4+2] + wsum[r*4+3]) * (1.f/128.f);
        out[(r0 + r)*128 + j] = (hid[r] - mu[r]) * rsqrtf(var + 1e-12f) * gj + bbj;
    }
}

// ---------------------------------------------------------------------------
extern "C" void kernel_launch(void* const* d_in, const int* in_sizes, int n_in,
                              void* d_out, int out_size)
{
    const float* X    = (const float*)d_in[0];
    const void*  tsq  = d_in[1];
    const float* mask = (const float*)d_in[2];
    const float* Wq   = (const float*)d_in[3];
    const float* bq   = (const float*)d_in[4];
    const float* Wk   = (const float*)d_in[5];
    const float* bk   = (const float*)d_in[6];
    const float* Wv   = (const float*)d_in[7];
    const float* bv   = (const float*)d_in[8];
    const float* Wd   = (const float*)d_in[9];
    const float* bd   = (const float*)d_in[10];
    const float* lng  = (const float*)d_in[11];
    const float* lnb  = (const float*)d_in[12];
    const float* KT   = (const float*)d_in[13];
    const float* VT   = (const float*)d_in[14];
    const float* kp   = (const float*)d_in[15];
    const float* vp   = (const float*)d_in[16];

    proj_kernel<<<dim3(100, 3), 128>>>(X, Wq, bq, Wk, bk, Wv, bv, kp, vp);

    const size_t smem = SMEM_FLOATS * sizeof(float);
    cudaFuncSetAttribute(attn_kernel, cudaFuncAttributeMaxDynamicSharedMemorySize, (int)smem);
    attn_kernel<<<dim3(8, NHD, BB), 256, smem>>>(mask, tsq, KT, VT);

    out_kernel<<<100, 128>>>(X, Wd, bd, lng, lnb, (float*)d_out);
}

// round 2
// speedup vs baseline: 2.1304x; 2.1304x over previous
#include <cuda_runtime.h>
#include <math.h>

#define HH   128
#define NHD  2
#define HDd  64
#define BB   8
#define LLs  200
#define TVC  32
#define NROWS (BB*LLs)   // 1600

// scratch (device globals: no allocation allowed)
__device__ float g_q  [NROWS*HH];
__device__ float g_kk [NROWS*HH];
__device__ float g_vv [NROWS*HH];
__device__ float g_ctx[NROWS*HH];

// ---------------------------------------------------------------------------
// Kernel 1: fused QKV projection (+bias, +pos tables folded into K and V)
// grid (200, 3), block 128.  8 rows/block; warp handles 2 rows, lane -> 4 cols
// ---------------------------------------------------------------------------
__global__ void proj_kernel(const float* __restrict__ X,
                            const float* __restrict__ Wq, const float* __restrict__ bq,
                            const float* __restrict__ Wk, const float* __restrict__ bk,
                            const float* __restrict__ Wv, const float* __restrict__ bv,
                            const float* __restrict__ kpos, const float* __restrict__ vpos)
{
    const int m    = blockIdx.y;
    const int rb   = blockIdx.x * 8;
    const int tid  = threadIdx.x;
    const int lane = tid & 31;
    const int wid  = tid >> 5;
    const int r0   = wid * 2;

    __shared__ float xs[8*128];
    {
        const float4* Xg4 = (const float4*)(X + (size_t)rb*128);
        ((float4*)xs)[tid]       = Xg4[tid];
        ((float4*)xs)[tid + 128] = Xg4[tid + 128];
    }
    __syncthreads();

    const float* W    = (m==0) ? Wq : (m==1 ? Wk : Wv);
    const float* bias = (m==0) ? bq : (m==1 ? bk : bv);
    const float4* W4  = (const float4*)W;

    float4 a0 = make_float4(0.f,0.f,0.f,0.f);
    float4 a1 = make_float4(0.f,0.f,0.f,0.f);

    #pragma unroll 8
    for (int i = 0; i < 128; i++) {
        float4 w = W4[i*32 + lane];
        float x0 = xs[r0*128 + i];
        float x1 = xs[r0*128 + 128 + i];
        a0.x += x0*w.x; a0.y += x0*w.y; a0.z += x0*w.z; a0.w += x0*w.w;
        a1.x += x1*w.x; a1.y += x1*w.y; a1.z += x1*w.z; a1.w += x1*w.w;
    }

    float4 bz = ((const float4*)bias)[lane];
    a0.x += bz.x; a0.y += bz.y; a0.z += bz.z; a0.w += bz.w;
    a1.x += bz.x; a1.y += bz.y; a1.z += bz.z; a1.w += bz.w;

    const int gr = rb + r0;
    if (m == 1) {
        float4 p0 = ((const float4*)kpos)[(gr % LLs)*32 + lane];
        float4 p1 = ((const float4*)kpos)[((gr+1) % LLs)*32 + lane];
        a0.x += p0.x; a0.y += p0.y; a0.z += p0.z; a0.w += p0.w;
        a1.x += p1.x; a1.y += p1.y; a1.z += p1.z; a1.w += p1.w;
    } else if (m == 2) {
        float4 p0 = ((const float4*)vpos)[(gr % LLs)*32 + lane];
        float4 p1 = ((const float4*)vpos)[((gr+1) % LLs)*32 + lane];
        a0.x += p0.x; a0.y += p0.y; a0.z += p0.z; a0.w += p0.w;
        a1.x += p1.x; a1.y += p1.y; a1.z += p1.z; a1.w += p1.w;
    }

    float* out = (m==0) ? g_q : (m==1 ? g_kk : g_vv);
    ((float4*)out)[(size_t)gr*32 + lane]     = a0;
    ((float4*)out)[(size_t)(gr+1)*32 + lane] = a1;
}

// ---------------------------------------------------------------------------
// Kernel 2: attention. grid (8 q-tiles, NH, B), block 256, dynamic smem.
// 5 q rows per iteration; binning via warp segmented scan + smem atomics.
// ---------------------------------------------------------------------------
#define SMEM_FLOATS 40624

__global__ void attn_kernel(const float* __restrict__ maskg,
                            const void*  __restrict__ tsq,
                            const float* __restrict__ KTg,
                            const float* __restrict__ VTg)
{
    extern __shared__ float sm[];
    const int qt   = blockIdx.x;       // 0..7 (25 q rows each)
    const int h    = blockIdx.y;
    const int b    = blockIdx.z;
    const int tid  = threadIdx.x;
    const int lane = tid & 31;
    const int wid  = tid >> 5;

    float* kk    = sm;              // 200*68
    float* vv    = sm + 13600;      // 200*68
    float* kt    = sm + 27200;      // 32*68
    float* vt    = sm + 29376;      // 32*68
    int*   tv    = (int*)(sm + 31552);  // 200
    float* qall  = sm + 31752;      // 25*64
    float* tsall = sm + 33352;      // 25*32
    float* pdA   = sm + 34152;      // 200*4 (float4 per k)
    float* pdB   = sm + 34952;      // 200
    float* cbinT = sm + 35152;      // 32*8
    float* pA    = sm + 35408;      // 5*8*32 float2
    float* pB    = sm + 37968;      // 5*8*32 float2
    float* red   = sm + 40528;      // 96

    // ---- stage K,V head slices (stride 68 -> conflict-free float4) ----
    const float* kkg = g_kk + (size_t)(b*LLs)*HH + h*HDd;
    const float* vvg = g_vv + (size_t)(b*LLs)*HH + h*HDd;
    for (int idx = tid; idx < LLs*16; idx += 256) {
        int k = idx >> 4, d4 = idx & 15;
        ((float4*)(kk + k*68))[d4] = ((const float4*)(kkg + k*HH))[d4];
        ((float4*)(vv + k*68))[d4] = ((const float4*)(vvg + k*HH))[d4];
    }
    for (int idx = tid; idx < TVC*16; idx += 256) {
        int w = idx >> 4, d4 = idx & 15;
        ((float4*)(kt + w*68))[d4] = ((const float4*)(KTg + w*HH + h*HDd))[d4];
        ((float4*)(vt + w*68))[d4] = ((const float4*)(VTg + w*HH + h*HDd))[d4];
    }
    // time values: detect int64 vs int32 storage (word 199 is the high word
    // of element 99 if int64 -> 0; the sorted max of row 0 if int32 -> >0).
    {
        const int* t32 = (const int*)tsq;
        bool is64 = (t32[199] == 0);
        for (int k = tid; k < LLs; k += 256)
            tv[k] = is64 ? (int)((const long long*)tsq)[b*LLs + k]
                         : t32[b*LLs + k];
    }
    // q rows for this tile
    {
        const float* qg = g_q + (size_t)(b*LLs)*HH + h*HDd;
        for (int idx = tid; idx < 25*16; idx += 256) {
            int q = idx >> 4, d4 = idx & 15;
            ((float4*)(qall + q*64))[d4] = ((const float4*)(qg + (qt*25+q)*HH))[d4];
        }
    }
    cbinT[tid] = 0.f;
    __syncthreads();

    // ---- ts_all[q][w] = q . KT[w] for all 25 q of this tile ----
    for (int i = tid; i < 25*32; i += 256) {
        int q = i >> 5, w = i & 31;
        const float4* q4 = (const float4*)(qall + q*64);
        const float4* kr = (const float4*)(kt + w*68);
        float a = 0.f;
        #pragma unroll
        for (int j = 0; j < 16; j++) {
            float4 x = q4[j], y = kr[j];
            a += x.x*y.x + x.y*y.y + x.z*y.z + x.w*y.w;
        }
        tsall[i] = a;
    }
    __syncthreads();

    const unsigned wmask    = (wid < 6) ? 0xFFFFFFFFu : 0x000000FFu;
    const int      lastlane = (wid < 6) ? 31 : 7;

    for (int it = 0; it < 5; it++) {
        const int q0    = it*5;
        const int qbase = qt*25 + q0;

        float s[5], e[5];
        #pragma unroll
        for (int q = 0; q < 5; q++) { s[q] = -1e30f; e[q] = 0.f; }

        const int k = tid;
        if (k < LLs) {
            float a[5]; int ix[5];
            #pragma unroll
            for (int q = 0; q < 5; q++) a[q] = 0.f;

            const float4* kr = (const float4*)(kk + k*68);
            #pragma unroll
            for (int j = 0; j < 16; j++) {
                float4 y = kr[j];
                #pragma unroll
                for (int q = 0; q < 5; q++) {
                    float4 x = ((const float4*)(qall + (q0+q)*64))[j];
                    a[q] += x.x*y.x + x.y*y.y + x.z*y.z + x.w*y.w;
                }
            }

            const int tk = tv[k];
            const float* mrow = maskg + ((size_t)(b*LLs) + qbase)*LLs + k;
            #pragma unroll
            for (int q = 0; q < 5; q++) {
                int dt = tv[qbase+q] - tk; if (dt < 0) dt = -dt;
                int ixq = (int)log1pf((float)dt);
                float sv = (a[q] + tsall[(q0+q)*32 + ixq])*0.125f + mrow[q*LLs];
                s[q] = sv; ix[q] = ixq;
            }

            // binning: cbinT[w][q] += s  via warp segmented scan + atomics
            #pragma unroll
            for (int q = 0; q < 5; q++) {
                int   ixq = ix[q];
                float v   = s[q];
                int prev  = __shfl_up_sync(wmask, ixq, 1);
                bool head = (lane == 0) || (prev != ixq);
                unsigned hb = __ballot_sync(wmask, head);
                unsigned le = 0xFFFFFFFFu >> (31 - lane);
                int headlane = 31 - __clz(hb & le);
                int run = lane - headlane;
                #pragma unroll
                for (int d = 1; d < 32; d <<= 1) {
                    float t = __shfl_up_sync(wmask, v, d);
                    if (run >= d) v += t;
                }
                bool tail = (lane == lastlane) || ((hb & (2u << lane)) != 0u);
                if (tail) atomicAdd(&cbinT[ixq*8 + q], v);
            }
        }

        // ---- softmax: block max then sum (5 q's simultaneously) ----
        #pragma unroll
        for (int q = 0; q < 5; q++) {
            float m = s[q];
            #pragma unroll
            for (int o = 16; o > 0; o >>= 1)
                m = fmaxf(m, __shfl_xor_sync(0xFFFFFFFFu, m, o));
            if (lane == 0) red[q*8 + wid] = m;
        }
        __syncthreads();
        if (tid < 5) {
            float m = red[tid*8];
            #pragma unroll
            for (int i = 1; i < 8; i++) m = fmaxf(m, red[tid*8 + i]);
            red[40 + tid] = m;
        }
        __syncthreads();

        if (k < LLs) {
            #pragma unroll
            for (int q = 0; q < 5; q++) e[q] = __expf(s[q] - red[40+q]);
        }
        #pragma unroll
        for (int q = 0; q < 5; q++) {
            float se = e[q];
            #pragma unroll
            for (int o = 16; o > 0; o >>= 1)
                se += __shfl_xor_sync(0xFFFFFFFFu, se, o);
            if (lane == 0) red[q*8 + wid] = se;
        }
        __syncthreads();
        if (tid < 5) {
            float se = 0.f;
            #pragma unroll
            for (int i = 0; i < 8; i++) se += red[tid*8 + i];
            red[48 + tid] = 1.f / se;
        }
        __syncthreads();

        if (k < LLs) {
            float4 p;
            p.x = e[0]*red[48]; p.y = e[1]*red[49];
            p.z = e[2]*red[50]; p.w = e[3]*red[51];
            ((float4*)pdA)[k] = p;
            pdB[k] = e[4]*red[52];
        }
        __syncthreads();   // pd + cbinT atomics visible

        // ---- context partials: ctx = p @ vv + cbin @ vt ----
        {
            const int kc = wid, d2 = lane;
            float2 acc[5];
            #pragma unroll
            for (int q = 0; q < 5; q++) { acc[q].x = 0.f; acc[q].y = 0.f; }
            const int kb = kc*25;
            #pragma unroll 5
            for (int kk2 = 0; kk2 < 25; kk2++) {
                int kx = kb + kk2;
                float2 v  = *(const float2*)(vv + kx*68 + 2*d2);
                float4 p4 = ((const float4*)pdA)[kx];
                float  pb = pdB[kx];
                acc[0].x += p4.x*v.x; acc[0].y += p4.x*v.y;
                acc[1].x += p4.y*v.x; acc[1].y += p4.y*v.y;
                acc[2].x += p4.z*v.x; acc[2].y += p4.z*v.y;
                acc[3].x += p4.w*v.x; acc[3].y += p4.w*v.y;
                acc[4].x += pb  *v.x; acc[4].y += pb  *v.y;
            }
            float2 acct[5];
            #pragma unroll
            for (int q = 0; q < 5; q++) { acct[q].x = 0.f; acct[q].y = 0.f; }
            #pragma unroll
            for (int wv = kc*4; wv < kc*4 + 4; wv++) {
                float2 tvv = *(const float2*)(vt + wv*68 + 2*d2);
                float4 c4  = *(const float4*)(cbinT + wv*8);
                float  cb  = cbinT[wv*8 + 4];
                acct[0].x += c4.x*tvv.x; acct[0].y += c4.x*tvv.y;
                acct[1].x += c4.y*tvv.x; acct[1].y += c4.y*tvv.y;
                acct[2].x += c4.z*tvv.x; acct[2].y += c4.z*tvv.y;
                acct[3].x += c4.w*tvv.x; acct[3].y += c4.w*tvv.y;
                acct[4].x += cb  *tvv.x; acct[4].y += cb  *tvv.y;
            }
            #pragma unroll
            for (int q = 0; q < 5; q++) {
                ((float2*)pA)[(q*8 + kc)*32 + d2] = acc[q];
                ((float2*)pB)[(q*8 + kc)*32 + d2] = acct[q];
            }
        }
        __syncthreads();

        if (tid < 160) {
            int q = tid >> 5, d2 = tid & 31;
            float2 a; a.x = 0.f; a.y = 0.f;
            #pragma unroll
            for (int kc = 0; kc < 8; kc++) {
                float2 x = ((float2*)pA)[(q*8 + kc)*32 + d2];
                float2 y = ((float2*)pB)[(q*8 + kc)*32 + d2];
                a.x += x.x + y.x; a.y += x.y + y.y;
            }
            *(float2*)(g_ctx + ((size_t)(b*LLs) + qbase + q)*HH + h*HDd + 2*d2) = a;
        }
        cbinT[tid] = 0.f;   // reset bins for next iteration
        __syncthreads();
    }
}

// ---------------------------------------------------------------------------
// Kernel 3: output projection + bias + residual + LayerNorm (warp-local LN)
// grid 200, block 128; 8 rows/block; warp -> 2 rows, lane -> 4 cols
// ---------------------------------------------------------------------------
__global__ void out_kernel(const float* __restrict__ X,
                           const float* __restrict__ Wd, const float* __restrict__ bd,
                           const float* __restrict__ lng, const float* __restrict__ lnb,
                           float* __restrict__ out)
{
    const int rb   = blockIdx.x * 8;
    const int tid  = threadIdx.x;
    const int lane = tid & 31;
    const int wid  = tid >> 5;
    const int r0   = wid * 2;

    __shared__ float cs[8*128];
    {
        const float4* Cg4 = (const float4*)(g_ctx + (size_t)rb*128);
        ((float4*)cs)[tid]       = Cg4[tid];
        ((float4*)cs)[tid + 128] = Cg4[tid + 128];
    }
    __syncthreads();

    const float4* W4 = (const float4*)Wd;
    float4 a0 = make_float4(0.f,0.f,0.f,0.f);
    float4 a1 = make_float4(0.f,0.f,0.f,0.f);

    #pragma unroll 8
    for (int i = 0; i < 128; i++) {
        float4 w = W4[i*32 + lane];
        float x0 = cs[r0*128 + i];
        float x1 = cs[r0*128 + 128 + i];
        a0.x += x0*w.x; a0.y += x0*w.y; a0.z += x0*w.z; a0.w += x0*w.w;
        a1.x += x1*w.x; a1.y += x1*w.y; a1.z += x1*w.z; a1.w += x1*w.w;
    }

    float4 bz = ((const float4*)bd)[lane];
    float4 x0 = ((const float4*)X)[(size_t)(rb+r0)*32 + lane];
    float4 x1 = ((const float4*)X)[(size_t)(rb+r0+1)*32 + lane];

    float4 h0, h1;
    h0.x = a0.x + bz.x + x0.x; h0.y = a0.y + bz.y + x0.y;
    h0.z = a0.z + bz.z + x0.z; h0.w = a0.w + bz.w + x0.w;
    h1.x = a1.x + bz.x + x1.x; h1.y = a1.y + bz.y + x1.y;
    h1.z = a1.z + bz.z + x1.z; h1.w = a1.w + bz.w + x1.w;

    // mean (warp-local: 32 lanes x 4 cols = full row)
    float s0 = h0.x + h0.y + h0.z + h0.w;
    float s1 = h1.x + h1.y + h1.z + h1.w;
    #pragma unroll
    for (int o = 16; o > 0; o >>= 1) {
        s0 += __shfl_xor_sync(0xFFFFFFFFu, s0, o);
        s1 += __shfl_xor_sync(0xFFFFFFFFu, s1, o);
    }
    float mu0 = s0 * (1.f/128.f), mu1 = s1 * (1.f/128.f);

    float d, v0 = 0.f, v1 = 0.f;
    d = h0.x-mu0; v0 += d*d; d = h0.y-mu0; v0 += d*d;
    d = h0.z-mu0; v0 += d*d; d = h0.w-mu0; v0 += d*d;
    d = h1.x-mu1; v1 += d*d; d = h1.y-mu1; v1 += d*d;
    d = h1.z-mu1; v1 += d*d; d = h1.w-mu1; v1 += d*d;
    #pragma unroll
    for (int o = 16; o > 0; o >>= 1) {
        v0 += __shfl_xor_sync(0xFFFFFFFFu, v0, o);
        v1 += __shfl_xor_sync(0xFFFFFFFFu, v1, o);
    }
    float is0 = rsqrtf(v0 * (1.f/128.f) + 1e-12f);
    float is1 = rsqrtf(v1 * (1.f/128.f) + 1e-12f);

    float4 g  = ((const float4*)lng)[lane];
    float4 bb = ((const float4*)lnb)[lane];

    float4 o0, o1;
    o0.x = (h0.x-mu0)*is0*g.x + bb.x; o0.y = (h0.y-mu0)*is0*g.y + bb.y;
    o0.z = (h0.z-mu0)*is0*g.z + bb.z; o0.w = (h0.w-mu0)*is0*g.w + bb.w;
    o1.x = (h1.x-mu1)*is1*g.x + bb.x; o1.y = (h1.y-mu1)*is1*g.y + bb.y;
    o1.z = (h1.z-mu1)*is1*g.z + bb.z; o1.w = (h1.w-mu1)*is1*g.w + bb.w;

    ((float4*)out)[(size_t)(rb+r0)*32 + lane]   = o0;
    ((float4*)out)[(size_t)(rb+r0+1)*32 + lane] = o1;
}

// ---------------------------------------------------------------------------
extern "C" void kernel_launch(void* const* d_in, const int* in_sizes, int n_in,
                              void* d_out, int out_size)
{
    const float* X    = (const float*)d_in[0];
    const void*  tsq  = d_in[1];
    const float* mask = (const float*)d_in[2];
    const float* Wq   = (const float*)d_in[3];
    const float* bq   = (const float*)d_in[4];
    const float* Wk   = (const float*)d_in[5];
    const float* bk   = (const float*)d_in[6];
    const float* Wv   = (const float*)d_in[7];
    const float* bv   = (const float*)d_in[8];
    const float* Wd   = (const float*)d_in[9];
    const float* bd   = (const float*)d_in[10];
    const float* lng  = (const float*)d_in[11];
    const float* lnb  = (const float*)d_in[12];
    const float* KT   = (const float*)d_in[13];
    const float* VT   = (const float*)d_in[14];
    const float* kp   = (const float*)d_in[15];
    const float* vp   = (const float*)d_in[16];

    proj_kernel<<<dim3(200, 3), 128>>>(X, Wq, bq, Wk, bk, Wv, bv, kp, vp);

    const size_t smem = SMEM_FLOATS * sizeof(float);
    cudaFuncSetAttribute(attn_kernel, cudaFuncAttributeMaxDynamicSharedMemorySize, (int)smem);
    attn_kernel<<<dim3(8, NHD, BB), 256, smem>>>(mask, tsq, KT, VT);

    out_kernel<<<200, 128>>>(X, Wd, bd, lng, lnb, (float*)d_out);
}

// round 4
// speedup vs baseline: 2.6350x; 1.2369x over previous
#include <cuda_runtime.h>
#include <stdint.h>
#include <math.h>

#define HH   128
#define NHD  2
#define HDd  64
#define BB   8
#define LLs  200
#define TVC  32
#define NROWS (BB*LLs)   // 1600

typedef unsigned long long ull;

// scratch (device globals: no allocation allowed)
__device__ float g_q  [NROWS*HH];
__device__ float g_kk [NROWS*HH];
__device__ float g_vv [NROWS*HH];
__device__ float g_ctx[NROWS*HH];

// ---- helpers --------------------------------------------------------------
__device__ __forceinline__ void cp16(uint32_t s, const void* g) {
    asm volatile("cp.async.cg.shared.global [%0], [%1], 16;" :: "r"(s), "l"(g));
}
__device__ __forceinline__ void cp_commit_wait() {
    asm volatile("cp.async.commit_group;");
    asm volatile("cp.async.wait_group 0;" ::: "memory");
}
__device__ __forceinline__ ull pk2(float x) {
    ull r; asm("mov.b64 %0,{%1,%1};" : "=l"(r) : "f"(x)); return r;
}
__device__ __forceinline__ void fma2(ull& d, ull a, ull b) {
    asm("fma.rn.f32x2 %0,%1,%2,%0;" : "+l"(d) : "l"(a), "l"(b));
}
__device__ __forceinline__ float f2lo(ull v) {
    float a, b; asm("mov.b64 {%0,%1},%2;" : "=f"(a), "=f"(b) : "l"(v)); return a;
}
__device__ __forceinline__ float f2hi(ull v) {
    float a, b; asm("mov.b64 {%0,%1},%2;" : "=f"(a), "=f"(b) : "l"(v)); return b;
}

extern __shared__ float smem_dyn[];

// ---------------------------------------------------------------------------
// Kernel 1: fused QKV projection (+bias, +pos tables folded into K and V)
// grid (100, 3), block 128.  16 rows/block; warp -> 4 rows, lane -> 4 cols.
// W + X staged via cp.async; math in fma.rn.f32x2 (col pairs).
// ---------------------------------------------------------------------------
#define GEMM_STEP(comp, ioff)                                                 \
    {                                                                         \
        ulonglong2 wv = ws2[(i0 + ioff)*32 + lane];                           \
        ull p;                                                                \
        p = pk2(xr0.comp); fma2(acc00, p, wv.x); fma2(acc01, p, wv.y);        \
        p = pk2(xr1.comp); fma2(acc10, p, wv.x); fma2(acc11, p, wv.y);        \
        p = pk2(xr2.comp); fma2(acc20, p, wv.x); fma2(acc21, p, wv.y);        \
        p = pk2(xr3.comp); fma2(acc30, p, wv.x); fma2(acc31, p, wv.y);        \
    }

__global__ void __launch_bounds__(128, 1)
proj_kernel(const float* __restrict__ X,
            const float* __restrict__ Wq, const float* __restrict__ bq,
            const float* __restrict__ Wk, const float* __restrict__ bk,
            const float* __restrict__ Wv, const float* __restrict__ bv,
            const float* __restrict__ kpos, const float* __restrict__ vpos)
{
    const int m    = blockIdx.y;
    const int rb   = blockIdx.x * 16;
    const int tid  = threadIdx.x;
    const int lane = tid & 31;
    const int wid  = tid >> 5;

    float* xs = smem_dyn;          // 16*128
    float* ws = smem_dyn + 2048;   // 128*128

    const float* W    = (m==0) ? Wq : (m==1 ? Wk : Wv);
    const float* bias = (m==0) ? bq : (m==1 ? bk : bv);

    // ---- stage X tile + full W via cp.async --------------------------------
    {
        uint32_t xs_s = (uint32_t)__cvta_generic_to_shared(xs);
        uint32_t ws_s = (uint32_t)__cvta_generic_to_shared(ws);
        const float4* Xg = (const float4*)(X + (size_t)rb*128);
        const float4* Wg = (const float4*)W;
        #pragma unroll
        for (int j = 0; j < 4; j++)
            cp16(xs_s + (tid + 128*j)*16, Xg + tid + 128*j);
        #pragma unroll
        for (int j = 0; j < 32; j++)
            cp16(ws_s + (tid + 128*j)*16, Wg + tid + 128*j);
        cp_commit_wait();
    }
    __syncthreads();

    const int r0 = wid * 4;
    ull acc00=0, acc01=0, acc10=0, acc11=0, acc20=0, acc21=0, acc30=0, acc31=0;
    const ulonglong2* ws2 = (const ulonglong2*)ws;

    for (int i0 = 0; i0 < 128; i0 += 4) {
        float4 xr0 = *(const float4*)(xs + (r0+0)*128 + i0);
        float4 xr1 = *(const float4*)(xs + (r0+1)*128 + i0);
        float4 xr2 = *(const float4*)(xs + (r0+2)*128 + i0);
        float4 xr3 = *(const float4*)(xs + (r0+3)*128 + i0);
        GEMM_STEP(x, 0)
        GEMM_STEP(y, 1)
        GEMM_STEP(z, 2)
        GEMM_STEP(w, 3)
    }

    float4 bz = ((const float4*)bias)[lane];
    float* outg = (m==0) ? g_q : (m==1 ? g_kk : g_vv);
    const float* pos = (m==1) ? kpos : vpos;

    ull aL[4] = {acc00, acc10, acc20, acc30};
    ull aH[4] = {acc01, acc11, acc21, acc31};
    #pragma unroll
    for (int r = 0; r < 4; r++) {
        const int gr = rb + r0 + r;
        float4 o;
        o.x = f2lo(aL[r]) + bz.x;
        o.y = f2hi(aL[r]) + bz.y;
        o.z = f2lo(aH[r]) + bz.z;
        o.w = f2hi(aH[r]) + bz.w;
        if (m != 0) {
            float4 p = ((const float4*)pos)[(gr % LLs)*32 + lane];
            o.x += p.x; o.y += p.y; o.z += p.z; o.w += p.w;
        }
        ((float4*)outg)[(size_t)gr*32 + lane] = o;
    }
}

// ---------------------------------------------------------------------------
// Kernel 2: attention. grid (8 q-tiles, NH, B), block 256, dynamic smem.
// 5 q rows per iteration; binning via warp segmented scan + smem atomics.
// ---------------------------------------------------------------------------
#define SMEM_FLOATS 40624

__global__ void attn_kernel(const float* __restrict__ maskg,
                            const void*  __restrict__ tsq,
                            const float* __restrict__ KTg,
                            const float* __restrict__ VTg)
{
    float* sm = smem_dyn;
    const int qt   = blockIdx.x;       // 0..7 (25 q rows each)
    const int h    = blockIdx.y;
    const int b    = blockIdx.z;
    const int tid  = threadIdx.x;
    const int lane = tid & 31;
    const int wid  = tid >> 5;

    float* kk    = sm;              // 200*68
    float* vv    = sm + 13600;      // 200*68
    float* kt    = sm + 27200;      // 32*68
    float* vt    = sm + 29376;      // 32*68
    int*   tv    = (int*)(sm + 31552);  // 200
    float* qall  = sm + 31752;      // 25*64
    float* tsall = sm + 33352;      // 25*32
    float* pdA   = sm + 34152;      // 200*4 (float4 per k)
    float* pdB   = sm + 34952;      // 200
    float* cbinT = sm + 35152;      // 32*8
    float* pA    = sm + 35408;      // 5*8*32 float2
    float* pB    = sm + 37968;      // 5*8*32 float2
    float* red   = sm + 40528;      // 96

    // ---- stage K,V head slices (stride 68 -> conflict-free float4) ----
    const float* kkg = g_kk + (size_t)(b*LLs)*HH + h*HDd;
    const float* vvg = g_vv + (size_t)(b*LLs)*HH + h*HDd;
    for (int idx = tid; idx < LLs*16; idx += 256) {
        int k = idx >> 4, d4 = idx & 15;
        ((float4*)(kk + k*68))[d4] = ((const float4*)(kkg + k*HH))[d4];
        ((float4*)(vv + k*68))[d4] = ((const float4*)(vvg + k*HH))[d4];
    }
    for (int idx = tid; idx < TVC*16; idx += 256) {
        int w = idx >> 4, d4 = idx & 15;
        ((float4*)(kt + w*68))[d4] = ((const float4*)(KTg + w*HH + h*HDd))[d4];
        ((float4*)(vt + w*68))[d4] = ((const float4*)(VTg + w*HH + h*HDd))[d4];
    }
    // time values: detect int64 vs int32 storage (word 199 is the high word
    // of element 99 if int64 -> 0; the sorted max of row 0 if int32 -> >0).
    {
        const int* t32 = (const int*)tsq;
        bool is64 = (t32[199] == 0);
        for (int k = tid; k < LLs; k += 256)
            tv[k] = is64 ? (int)((const long long*)tsq)[b*LLs + k]
                         : t32[b*LLs + k];
    }
    // q rows for this tile
    {
        const float* qg = g_q + (size_t)(b*LLs)*HH + h*HDd;
        for (int idx = tid; idx < 25*16; idx += 256) {
            int q = idx >> 4, d4 = idx & 15;
            ((float4*)(qall + q*64))[d4] = ((const float4*)(qg + (qt*25+q)*HH))[d4];
        }
    }
    cbinT[tid] = 0.f;
    __syncthreads();

    // ---- ts_all[q][w] = q . KT[w] for all 25 q of this tile ----
    for (int i = tid; i < 25*32; i += 256) {
        int q = i >> 5, w = i & 31;
        const float4* q4 = (const float4*)(qall + q*64);
        const float4* kr = (const float4*)(kt + w*68);
        float a = 0.f;
        #pragma unroll
        for (int j = 0; j < 16; j++) {
            float4 x = q4[j], y = kr[j];
            a += x.x*y.x + x.y*y.y + x.z*y.z + x.w*y.w;
        }
        tsall[i] = a;
    }
    __syncthreads();

    const unsigned wmask    = (wid < 6) ? 0xFFFFFFFFu : 0x000000FFu;
    const int      lastlane = (wid < 6) ? 31 : 7;

    for (int it = 0; it < 5; it++) {
        const int q0    = it*5;
        const int qbase = qt*25 + q0;

        float s[5], e[5];
        #pragma unroll
        for (int q = 0; q < 5; q++) { s[q] = -1e30f; e[q] = 0.f; }

        const int k = tid;
        if (k < LLs) {
            float a[5]; int ix[5];
            #pragma unroll
            for (int q = 0; q < 5; q++) a[q] = 0.f;

            const float4* kr = (const float4*)(kk + k*68);
            #pragma unroll
            for (int j = 0; j < 16; j++) {
                float4 y = kr[j];
                #pragma unroll
                for (int q = 0; q < 5; q++) {
                    float4 x = ((const float4*)(qall + (q0+q)*64))[j];
                    a[q] += x.x*y.x + x.y*y.y + x.z*y.z + x.w*y.w;
                }
            }

            const int tk = tv[k];
            const float* mrow = maskg + ((size_t)(b*LLs) + qbase)*LLs + k;
            #pragma unroll
            for (int q = 0; q < 5; q++) {
                int dt = tv[qbase+q] - tk; if (dt < 0) dt = -dt;
                int ixq = (int)log1pf((float)dt);
                float sv = (a[q] + tsall[(q0+q)*32 + ixq])*0.125f + mrow[q*LLs];
                s[q] = sv; ix[q] = ixq;
            }

            // binning: cbinT[w][q] += s  via warp segmented scan + atomics
            #pragma unroll
            for (int q = 0; q < 5; q++) {
                int   ixq = ix[q];
                float v   = s[q];
                int prev  = __shfl_up_sync(wmask, ixq, 1);
                bool head = (lane == 0) || (prev != ixq);
                unsigned hb = __ballot_sync(wmask, head);
                unsigned le = 0xFFFFFFFFu >> (31 - lane);
                int headlane = 31 - __clz(hb & le);
                int run = lane - headlane;
                #pragma unroll
                for (int d = 1; d < 32; d <<= 1) {
                    float t = __shfl_up_sync(wmask, v, d);
                    if (run >= d) v += t;
                }
                bool tail = (lane == lastlane) || ((hb & (2u << lane)) != 0u);
                if (tail) atomicAdd(&cbinT[ixq*8 + q], v);
            }
        }

        // ---- softmax: block max then sum (5 q's simultaneously) ----
        #pragma unroll
        for (int q = 0; q < 5; q++) {
            float m = s[q];
            #pragma unroll
            for (int o = 16; o > 0; o >>= 1)
                m = fmaxf(m, __shfl_xor_sync(0xFFFFFFFFu, m, o));
            if (lane == 0) red[q*8 + wid] = m;
        }
        __syncthreads();
        if (tid < 5) {
            float m = red[tid*8];
            #pragma unroll
            for (int i = 1; i < 8; i++) m = fmaxf(m, red[tid*8 + i]);
            red[40 + tid] = m;
        }
        __syncthreads();

        if (k < LLs) {
            #pragma unroll
            for (int q = 0; q < 5; q++) e[q] = __expf(s[q] - red[40+q]);
        }
        #pragma unroll
        for (int q = 0; q < 5; q++) {
            float se = e[q];
            #pragma unroll
            for (int o = 16; o > 0; o >>= 1)
                se += __shfl_xor_sync(0xFFFFFFFFu, se, o);
            if (lane == 0) red[q*8 + wid] = se;
        }
        __syncthreads();
        if (tid < 5) {
            float se = 0.f;
            #pragma unroll
            for (int i = 0; i < 8; i++) se += red[tid*8 + i];
            red[48 + tid] = 1.f / se;
        }
        __syncthreads();

        if (k < LLs) {
            float4 p;
            p.x = e[0]*red[48]; p.y = e[1]*red[49];
            p.z = e[2]*red[50]; p.w = e[3]*red[51];
            ((float4*)pdA)[k] = p;
            pdB[k] = e[4]*red[52];
        }
        __syncthreads();   // pd + cbinT atomics visible

        // ---- context partials: ctx = p @ vv + cbin @ vt ----
        {
            const int kc = wid, d2 = lane;
            float2 acc[5];
            #pragma unroll
            for (int q = 0; q < 5; q++) { acc[q].x = 0.f; acc[q].y = 0.f; }
            const int kb = kc*25;
            #pragma unroll 5
            for (int kk2 = 0; kk2 < 25; kk2++) {
                int kx = kb + kk2;
                float2 v  = *(const float2*)(vv + kx*68 + 2*d2);
                float4 p4 = ((const float4*)pdA)[kx];
                float  pb = pdB[kx];
                acc[0].x += p4.x*v.x; acc[0].y += p4.x*v.y;
                acc[1].x += p4.y*v.x; acc[1].y += p4.y*v.y;
                acc[2].x += p4.z*v.x; acc[2].y += p4.z*v.y;
                acc[3].x += p4.w*v.x; acc[3].y += p4.w*v.y;
                acc[4].x += pb  *v.x; acc[4].y += pb  *v.y;
            }
            float2 acct[5];
            #pragma unroll
            for (int q = 0; q < 5; q++) { acct[q].x = 0.f; acct[q].y = 0.f; }
            #pragma unroll
            for (int wv = kc*4; wv < kc*4 + 4; wv++) {
                float2 tvv = *(const float2*)(vt + wv*68 + 2*d2);
                float4 c4  = *(const float4*)(cbinT + wv*8);
                float  cb  = cbinT[wv*8 + 4];
                acct[0].x += c4.x*tvv.x; acct[0].y += c4.x*tvv.y;
                acct[1].x += c4.y*tvv.x; acct[1].y += c4.y*tvv.y;
                acct[2].x += c4.z*tvv.x; acct[2].y += c4.z*tvv.y;
                acct[3].x += c4.w*tvv.x; acct[3].y += c4.w*tvv.y;
                acct[4].x += cb  *tvv.x; acct[4].y += cb  *tvv.y;
            }
            #pragma unroll
            for (int q = 0; q < 5; q++) {
                ((float2*)pA)[(q*8 + kc)*32 + d2] = acc[q];
                ((float2*)pB)[(q*8 + kc)*32 + d2] = acct[q];
            }
        }
        __syncthreads();

        if (tid < 160) {
            int q = tid >> 5, d2 = tid & 31;
            float2 a; a.x = 0.f; a.y = 0.f;
            #pragma unroll
            for (int kc = 0; kc < 8; kc++) {
                float2 x = ((float2*)pA)[(q*8 + kc)*32 + d2];
                float2 y = ((float2*)pB)[(q*8 + kc)*32 + d2];
                a.x += x.x + y.x; a.y += x.y + y.y;
            }
            *(float2*)(g_ctx + ((size_t)(b*LLs) + qbase + q)*HH + h*HDd + 2*d2) = a;
        }
        cbinT[tid] = 0.f;   // reset bins for next iteration
        __syncthreads();
    }
}

// ---------------------------------------------------------------------------
// Kernel 3: output projection + bias + residual + LayerNorm (warp-local LN)
// grid 100, block 128; 16 rows/block; warp -> 4 rows, lane -> 4 cols.
// Wd + ctx tile staged via cp.async; math in fma.rn.f32x2.
// ---------------------------------------------------------------------------
__global__ void __launch_bounds__(128, 1)
out_kernel(const float* __restrict__ X,
           const float* __restrict__ Wd, const float* __restrict__ bd,
           const float* __restrict__ lng, const float* __restrict__ lnb,
           float* __restrict__ out)
{
    const int rb   = blockIdx.x * 16;
    const int tid  = threadIdx.x;
    const int lane = tid & 31;
    const int wid  = tid >> 5;

    float* xs = smem_dyn;          // 16*128 (ctx tile)
    float* ws = smem_dyn + 2048;   // 128*128

    {
        uint32_t xs_s = (uint32_t)__cvta_generic_to_shared(xs);
        uint32_t ws_s = (uint32_t)__cvta_generic_to_shared(ws);
        const float4* Cg = (const float4*)(g_ctx + (size_t)rb*128);
        const float4* Wg = (const float4*)Wd;
        #pragma unroll
        for (int j = 0; j < 4; j++)
            cp16(xs_s + (tid + 128*j)*16, Cg + tid + 128*j);
        #pragma unroll
        for (int j = 0; j < 32; j++)
            cp16(ws_s + (tid + 128*j)*16, Wg + tid + 128*j);
        cp_commit_wait();
    }
    __syncthreads();

    const int r0 = wid * 4;
    ull acc00=0, acc01=0, acc10=0, acc11=0, acc20=0, acc21=0, acc30=0, acc31=0;
    const ulonglong2* ws2 = (const ulonglong2*)ws;

    for (int i0 = 0; i0 < 128; i0 += 4) {
        float4 xr0 = *(const float4*)(xs + (r0+0)*128 + i0);
        float4 xr1 = *(const float4*)(xs + (r0+1)*128 + i0);
        float4 xr2 = *(const float4*)(xs + (r0+2)*128 + i0);
        float4 xr3 = *(const float4*)(xs + (r0+3)*128 + i0);
        GEMM_STEP(x, 0)
        GEMM_STEP(y, 1)
        GEMM_STEP(z, 2)
        GEMM_STEP(w, 3)
    }

    float4 bz = ((const float4*)bd)[lane];
    float4 g  = ((const float4*)lng)[lane];
    float4 bb = ((const float4*)lnb)[lane];

    ull aL[4] = {acc00, acc10, acc20, acc30};
    ull aH[4] = {acc01, acc11, acc21, acc31};

    #pragma unroll
    for (int r = 0; r < 4; r++) {
        const int gr = rb + r0 + r;
        float4 xg = ((const float4*)X)[(size_t)gr*32 + lane];
        float4 hv;
        hv.x = f2lo(aL[r]) + bz.x + xg.x;
        hv.y = f2hi(aL[r]) + bz.y + xg.y;
        hv.z = f2lo(aH[r]) + bz.z + xg.z;
        hv.w = f2hi(aH[r]) + bz.w + xg.w;

        float s = hv.x + hv.y + hv.z + hv.w;
        #pragma unroll
        for (int o = 16; o > 0; o >>= 1)
            s += __shfl_xor_sync(0xFFFFFFFFu, s, o);
        float mu = s * (1.f/128.f);

        float d, v = 0.f;
        d = hv.x - mu; v += d*d;
        d = hv.y - mu; v += d*d;
        d = hv.z - mu; v += d*d;
        d = hv.w - mu; v += d*d;
        #pragma unroll
        for (int o = 16; o > 0; o >>= 1)
            v += __shfl_xor_sync(0xFFFFFFFFu, v, o);
        float is = rsqrtf(v * (1.f/128.f) + 1e-12f);

        float4 o4;
        o4.x = (hv.x - mu)*is*g.x + bb.x;
        o4.y = (hv.y - mu)*is*g.y + bb.y;
        o4.z = (hv.z - mu)*is*g.z + bb.z;
        o4.w = (hv.w - mu)*is*g.w + bb.w;
        ((float4*)out)[(size_t)gr*32 + lane] = o4;
    }
}

// ---------------------------------------------------------------------------
extern "C" void kernel_launch(void* const* d_in, const int* in_sizes, int n_in,
                              void* d_out, int out_size)
{
    const float* X    = (const float*)d_in[0];
    const void*  tsq  = d_in[1];
    const float* mask = (const float*)d_in[2];
    const float* Wq   = (const float*)d_in[3];
    const float* bq   = (const float*)d_in[4];
    const float* Wk   = (const float*)d_in[5];
    const float* bk   = (const float*)d_in[6];
    const float* Wv   = (const float*)d_in[7];
    const float* bv   = (const float*)d_in[8];
    const float* Wd   = (const float*)d_in[9];
    const float* bd   = (const float*)d_in[10];
    const float* lng  = (const float*)d_in[11];
    const float* lnb  = (const float*)d_in[12];
    const float* KT   = (const float*)d_in[13];
    const float* VT   = (const float*)d_in[14];
    const float* kp   = (const float*)d_in[15];
    const float* vp   = (const float*)d_in[16];

    const size_t smem_gemm = (2048 + 16384) * sizeof(float);   // 73728
    const size_t smem_attn = SMEM_FLOATS * sizeof(float);       // 162496

    cudaFuncSetAttribute(proj_kernel, cudaFuncAttributeMaxDynamicSharedMemorySize, (int)smem_gemm);
    cudaFuncSetAttribute(out_kernel,  cudaFuncAttributeMaxDynamicSharedMemorySize, (int)smem_gemm);
    cudaFuncSetAttribute(attn_kernel, cudaFuncAttributeMaxDynamicSharedMemorySize, (int)smem_attn);

    proj_kernel<<<dim3(100, 3), 128, smem_gemm>>>(X, Wq, bq, Wk, bk, Wv, bv, kp, vp);
    attn_kernel<<<dim3(8, NHD, BB), 256, smem_attn>>>(mask, tsq, KT, VT);
    out_kernel<<<100, 128, smem_gemm>>>(X, Wd, bd, lng, lnb, (float*)d_out);
}